// round 16
// baseline (speedup 1.0000x reference)
#include <cuda_runtime.h>
#include <cuda_fp16.h>
#include <cstdint>

#define B_    4
#define T_    2048
#define H_    16
#define D_    64
#define MODEL 1024
#define DENOM 0.125f
#define NEG_INF (-1e30f)
#define L2E   1.4426950408889634f

// ---------------- scratch (allocation-free: device globals) ----------------
__device__ __half g_xq[(size_t)B_ * T_ * MODEL];
__device__ __half g_xk[(size_t)B_ * T_ * MODEL];
__device__ __half g_xv[(size_t)B_ * T_ * MODEL];
__device__ __half g_wq[(size_t)MODEL * MODEL];
__device__ __half g_wk[(size_t)MODEL * MODEL];
__device__ __half g_wv[(size_t)MODEL * MODEL];
__device__ __half g_wo[(size_t)MODEL * MODEL];
__device__ __half g_qh[(size_t)B_ * H_ * T_ * D_]; // Q, pre-scaled 0.125*log2e
__device__ __half g_kh[(size_t)B_ * H_ * T_ * D_]; // K [B,H,T,d]
__device__ __half g_vh[(size_t)B_ * H_ * T_ * D_]; // V [B,H,T,d]
__device__ __half g_ah[(size_t)B_ * T_ * H_ * D_]; // attn out [B,T,H,d]
// bitmask: word [b][kt][q] (kt = 64-key tile index), bit j = key kt*64+j
__device__ unsigned long long g_mb[(size_t)B_ * 32 * T_];

// ---------------------------------------------------------------------------
// Fused conversion kernel: first CVT_BLOCKS blocks do f32->f16 over 7 tensors;
// the last MASK_BLOCKS blocks sniff the mask dtype (first 4 KB) and bit-pack
// it into g_mb (64 keys per 64-bit word, layout [b][kt][q]).
// ---------------------------------------------------------------------------
#define NX4 (B_ * T_ * MODEL / 4)
#define NW4 (MODEL * MODEL / 4)
#define XBLK (NX4 / 256)
#define WBLK (NW4 / 256)
#define CVT_BLOCKS (3 * XBLK + 4 * WBLK)
#define MASK_BLOCKS ((B_ * 32 * T_) / 256)

struct CvtArgs {
    const float* in[7]; __half* out[7];
    const void* mask_in; unsigned long long* mask_out;
};

__global__ void cvt_all(CvtArgs a)
{
    int blk = blockIdx.x;
    const int tid = threadIdx.x;

    if (blk >= CVT_BLOCKS) {
        // ---- mask sniff + bitpack ----
        blk -= CVT_BLOCKS;
        __shared__ int red[8];
        __shared__ int s_flag;
        uint4 v = ((const uint4*)a.mask_in)[tid];   // first 4096 bytes
        const unsigned char* pb = (const unsigned char*)&v;
        int cnt = 0;
#pragma unroll
        for (int j = 0; j < 16; j++) cnt += (pb[j] != 0);
#pragma unroll
        for (int off = 16; off >= 1; off >>= 1)
            cnt += __shfl_xor_sync(0xffffffffu, cnt, off);
        if ((tid & 31) == 0) red[tid >> 5] = cnt;
        __syncthreads();
        if (tid == 0) {
            int total = 0;
#pragma unroll
            for (int w = 0; w < 8; w++) total += red[w];
            s_flag = (total > 1024) ? 1 : 0;        // 1 = byte mask
        }
        __syncthreads();

        const int w  = blk * 256 + tid;             // word index
        const int b  = w >> 16;
        const int kt = (w >> 11) & 31;
        const int q  = w & (T_ - 1);
        const size_t ebase = ((size_t)b * T_ + q) * T_ + kt * 64;

        unsigned long long bits = 0;
        if (s_flag) {
            const uint32_t* s32 =
                (const uint32_t*)((const unsigned char*)a.mask_in + ebase);
#pragma unroll
            for (int g = 0; g < 16; g++) {
                const uint32_t x = s32[g];
                if (x & 0x000000FFu) bits |= 1ull << (g * 4 + 0);
                if (x & 0x0000FF00u) bits |= 1ull << (g * 4 + 1);
                if (x & 0x00FF0000u) bits |= 1ull << (g * 4 + 2);
                if (x & 0xFF000000u) bits |= 1ull << (g * 4 + 3);
            }
        } else {
            const int* s32 = (const int*)a.mask_in + ebase;
#pragma unroll
            for (int g = 0; g < 64; g++)
                if (s32[g]) bits |= 1ull << g;
        }
        a.mask_out[w] = bits;
        return;
    }

    // ---- f32 -> f16 conversion ----
    int seg, base;
    if (blk < 3 * XBLK) { seg = blk / XBLK; base = (blk % XBLK); }
    else { blk -= 3 * XBLK; seg = 3 + blk / WBLK; base = (blk % WBLK); }
    const int i = base * 256 + tid;
    float4 f = ((const float4*)a.in[seg])[i];
    __half2* o = (__half2*)a.out[seg];
    o[2 * i]     = __floats2half2_rn(f.x, f.y);
    o[2 * i + 1] = __floats2half2_rn(f.z, f.w);
}

// ------------------------- ptx wrappers -------------------------
__device__ __forceinline__ uint32_t smem_u32(const void* p)
{ return (uint32_t)__cvta_generic_to_shared(p); }

__device__ __forceinline__ void cp16(void* s, const void* g)
{
    asm volatile("cp.async.cg.shared.global [%0], [%1], 16;\n"
                 :: "r"(smem_u32(s)), "l"(g));
}
__device__ __forceinline__ void cp_commit()
{ asm volatile("cp.async.commit_group;\n"); }
template<int N> __device__ __forceinline__ void cp_wait()
{ asm volatile("cp.async.wait_group %0;\n" :: "n"(N)); }

__device__ __forceinline__ void ldsm_x4(uint32_t* r, uint32_t addr)
{
    asm volatile("ldmatrix.sync.aligned.m8n8.x4.shared.b16 {%0,%1,%2,%3}, [%4];\n"
                 : "=r"(r[0]), "=r"(r[1]), "=r"(r[2]), "=r"(r[3]) : "r"(addr));
}
__device__ __forceinline__ void ldsm_x4_t(uint32_t* r, uint32_t addr)
{
    asm volatile("ldmatrix.sync.aligned.m8n8.x4.trans.shared.b16 {%0,%1,%2,%3}, [%4];\n"
                 : "=r"(r[0]), "=r"(r[1]), "=r"(r[2]), "=r"(r[3]) : "r"(addr));
}
__device__ __forceinline__ void mma16816(float* d, const uint32_t* a,
                                         uint32_t b0, uint32_t b1)
{
    asm volatile(
        "mma.sync.aligned.m16n8k16.row.col.f32.f16.f16.f32 "
        "{%0,%1,%2,%3}, {%4,%5,%6,%7}, {%8,%9}, {%0,%1,%2,%3};\n"
        : "+f"(d[0]), "+f"(d[1]), "+f"(d[2]), "+f"(d[3])
        : "r"(a[0]), "r"(a[1]), "r"(a[2]), "r"(a[3]), "r"(b0), "r"(b1));
}

__device__ __forceinline__ uint32_t h2ex2(uint32_t x)
{
    uint32_t r;
    asm volatile("ex2.approx.f16x2 %0, %1;" : "=r"(r) : "r"(x));
    return r;
}

// ---------------------------------------------------------------------------
// fp16 tensor-core GEMM, cp.async 2-stage pipeline (R4-proven, unchanged).
// ---------------------------------------------------------------------------
#define GEMM_SMEM ((2 * 128 * 72 + 2 * 64 * 136) * 2)   // 71680 B

template<int MODE>
__device__ __forceinline__ void gemm_body(
    const __half* __restrict__ X, const __half* __restrict__ W,
    const float* __restrict__ bias, void* __restrict__ out, float oscale,
    char* dynsm)
{
    typedef __half ARow[72];
    typedef __half BRow[136];
    ARow* As0 = (ARow*)dynsm;
    ARow* As1 = (ARow*)(dynsm + 128 * 72 * 2);
    BRow* Bs0 = (BRow*)(dynsm + 2 * 128 * 72 * 2);
    BRow* Bs1 = (BRow*)(dynsm + 2 * 128 * 72 * 2 + 64 * 136 * 2);

    const int tid  = threadIdx.x;
    const int lane = tid & 31;
    const int wid  = tid >> 5;
    const int warp_m = wid >> 2;
    const int warp_n = wid & 3;
    const int m0 = blockIdx.y * 128;
    const int n0 = blockIdx.x * 128;

    const int ar = tid >> 3, ac = (tid & 7) * 8;
    const int br = tid >> 4, bc = (tid & 15) * 8;

    float acc[4][4][4];
#pragma unroll
    for (int i = 0; i < 4; i++)
#pragma unroll
        for (int j = 0; j < 4; j++)
#pragma unroll
            for (int r = 0; r < 4; r++) acc[i][j][r] = 0.f;

    {
#pragma unroll
        for (int p = 0; p < 4; p++)
            cp16(&As0[p * 32 + ar][ac], &X[(size_t)(m0 + p * 32 + ar) * MODEL + ac]);
#pragma unroll
        for (int p = 0; p < 4; p++)
            cp16(&Bs0[p * 16 + br][bc], &W[(size_t)(p * 16 + br) * MODEL + n0 + bc]);
        cp_commit();
    }

    const int NI = MODEL / 64;
    for (int i = 0; i < NI; i++) {
        cp_wait<0>();
        __syncthreads();
        if (i + 1 < NI) {
            const int k0 = (i + 1) * 64;
            ARow* An = (i & 1) ? As0 : As1;
            BRow* Bn = (i & 1) ? Bs0 : Bs1;
#pragma unroll
            for (int p = 0; p < 4; p++)
                cp16(&An[p * 32 + ar][ac], &X[(size_t)(m0 + p * 32 + ar) * MODEL + k0 + ac]);
#pragma unroll
            for (int p = 0; p < 4; p++)
                cp16(&Bn[p * 16 + br][bc], &W[(size_t)(k0 + p * 16 + br) * MODEL + n0 + bc]);
            cp_commit();
        }
        ARow* Ac = (i & 1) ? As1 : As0;
        BRow* Bc = (i & 1) ? Bs1 : Bs0;
#pragma unroll
        for (int ks = 0; ks < 4; ks++) {
            uint32_t af[4][4];
#pragma unroll
            for (int mi = 0; mi < 4; mi++)
                ldsm_x4(af[mi], smem_u32(
                    &Ac[warp_m * 64 + mi * 16 + (lane & 15)][ks * 16 + (lane >> 4) * 8]));
#pragma unroll
            for (int nj = 0; nj < 2; nj++) {
                uint32_t bf[4];
                ldsm_x4_t(bf, smem_u32(
                    &Bc[ks * 16 + (lane & 15)][warp_n * 32 + nj * 16 + (lane >> 4) * 8]));
#pragma unroll
                for (int mi = 0; mi < 4; mi++) {
                    mma16816(acc[mi][nj * 2],     af[mi], bf[0], bf[1]);
                    mma16816(acc[mi][nj * 2 + 1], af[mi], bf[2], bf[3]);
                }
            }
        }
    }

#pragma unroll
    for (int mi = 0; mi < 4; mi++) {
#pragma unroll
        for (int ni = 0; ni < 4; ni++) {
            const int row = m0 + warp_m * 64 + mi * 16 + (lane >> 2);
            const int col = n0 + warp_n * 32 + ni * 8 + (lane & 3) * 2;
            const float b0 = bias[col], b1 = bias[col + 1];
            float c0 = acc[mi][ni][0] + b0, c1 = acc[mi][ni][1] + b1;
            float c2 = acc[mi][ni][2] + b0, c3 = acc[mi][ni][3] + b1;
            if (MODE) {
                c0 *= oscale; c1 *= oscale; c2 *= oscale; c3 *= oscale;
                const int bb = row >> 11, t = row & (T_ - 1);
                const int hh = col >> 6,  d = col & 63;
                __half2* o = (__half2*)out;
                const size_t base = ((((size_t)bb * H_ + hh) * T_) + t) * D_ + d;
                o[base >> 1] = __floats2half2_rn(c0, c1);
                const size_t base2 = base + (size_t)8 * D_;
                o[base2 >> 1] = __floats2half2_rn(c2, c3);
            } else {
                float* o = (float*)out;
                *(float2*)&o[(size_t)row * MODEL + col] = make_float2(c0, c1);
                *(float2*)&o[(size_t)(row + 8) * MODEL + col] = make_float2(c2, c3);
            }
        }
    }
}

struct QKVArgs {
    const __half* x[3];
    const __half* w[3];
    const float*  b[3];
    __half*       o[3];
    float         s[3];
};

__global__ __launch_bounds__(256, 2) void gemm_qkv(QKVArgs a)
{
    extern __shared__ char dynsm[];
    const int z = blockIdx.z;
    gemm_body<1>(a.x[z], a.w[z], a.b[z], a.o[z], a.s[z], dynsm);
}

__global__ __launch_bounds__(256, 2) void gemm_out(
    const __half* __restrict__ X, const __half* __restrict__ W,
    const float* __restrict__ bias, float* __restrict__ out)
{
    extern __shared__ char dynsm[];
    gemm_body<0>(X, W, bias, out, 1.0f, dynsm);
}

// ---------------------------------------------------------------------------
// Flash attention (R15 base: fixed-max softmax, bitmask, 2 CTAs/SM) with:
//  - log2e folded into Q projection (S arrives in log2 domain: no FMULs)
//  - l reduction deferred out of the loop (no per-iter shuffles)
// ---------------------------------------------------------------------------
struct AStage {
    __half k[64][72];
    __half v[64][72];
    unsigned long long msk[128];   // 1 KB bitmask
};  // 19456 B
#define ATTN_SMEM (128 * 72 * 2 + 2 * (int)sizeof(AStage))   // 57344 B

__global__ __launch_bounds__(256, 2) void mha_attn(
    const __half* __restrict__ qg, const __half* __restrict__ kg,
    const __half* __restrict__ vg, const unsigned long long* __restrict__ mbit,
    __half* __restrict__ out)
{
    extern __shared__ char dynsm[];
    typedef __half QRow[72];
    QRow* Qs = (QRow*)dynsm;                          // [128][72]
    AStage* st = (AStage*)(dynsm + 128 * 72 * 2);     // [2]

    const int tid  = threadIdx.x;
    const int lane = tid & 31;
    const int wid  = tid >> 5;
    const int q0 = blockIdx.x * 128;
    const int h  = blockIdx.y;
    const int b  = blockIdx.z;

    const __half* gq = qg + (((size_t)b * H_ + h) * T_ + q0) * D_;
    const __half* gk = kg + (((size_t)b * H_ + h) * T_) * D_;
    const __half* gv = vg + (((size_t)b * H_ + h) * T_) * D_;
    const unsigned long long* gmb = mbit + (size_t)b * 32 * T_ + q0;

    const int kvr = tid >> 3, kvc = (tid & 7) * 8;

    auto load_stage = [&](int kt, int stage) {
        AStage& ns = st[stage];
        const __half* gkt = gk + (size_t)kt * 64 * D_;
        const __half* gvt = gv + (size_t)kt * 64 * D_;
#pragma unroll
        for (int p = 0; p < 2; p++) {
            cp16(&ns.k[p * 32 + kvr][kvc], &gkt[(size_t)(p * 32 + kvr) * D_ + kvc]);
            cp16(&ns.v[p * 32 + kvr][kvc], &gvt[(size_t)(p * 32 + kvr) * D_ + kvc]);
        }
        if (tid < 64)
            cp16(&ns.msk[tid * 2], &gmb[(size_t)kt * T_ + tid * 2]);
    };

    // ---- prologue: Q tile, then stage 0 ----
#pragma unroll
    for (int p = 0; p < 4; p++)
        cp16(&Qs[p * 32 + kvr][kvc], &gq[(size_t)(p * 32 + kvr) * D_ + kvc]);
    cp_commit();
    load_stage(0, 0);
    cp_commit();

    cp_wait<1>();
    __syncthreads();
    uint32_t qf[4][4];
#pragma unroll
    for (int kc = 0; kc < 4; kc++)
        ldsm_x4(qf[kc], smem_u32(
            &Qs[wid * 16 + (lane & 15)][kc * 16 + (lane >> 4) * 8]));

    float oacc[8][4];
#pragma unroll
    for (int i = 0; i < 8; i++)
#pragma unroll
        for (int r = 0; r < 4; r++) oacc[i][r] = 0.f;
    float lrow[2] = {0.f, 0.f};    // per-thread partials; reduced after loop

    const int NT = T_ / 64;   // 32
    for (int kt = 0; kt < NT; kt++) {
        cp_wait<0>();
        __syncthreads();
        if (kt + 1 < NT) {
            load_stage(kt + 1, (kt + 1) & 1);
            cp_commit();
        }
        AStage& cs = st[kt & 1];

        // ---- S = Q K^T (Q pre-scaled by 0.125*log2e: S is log2-domain) ----
        float sv[8][4];
#pragma unroll
        for (int i = 0; i < 8; i++)
#pragma unroll
            for (int r = 0; r < 4; r++) sv[i][r] = 0.f;
#pragma unroll
        for (int nt2 = 0; nt2 < 4; nt2++) {
#pragma unroll
            for (int kc = 0; kc < 4; kc++) {
                uint32_t kf[4];
                ldsm_x4(kf, smem_u32(
                    &cs.k[nt2 * 16 + (lane & 15)][kc * 16 + (lane >> 4) * 8]));
                mma16816(sv[nt2 * 2],     qf[kc], kf[0], kf[2]);
                mma16816(sv[nt2 * 2 + 1], qf[kc], kf[1], kf[3]);
            }
        }

        // ---- bitmask fetch: 2 x LDS.64, pre-shift by this thread's column ----
        const int rl = wid * 16 + (lane >> 2);
        const unsigned long long w0 = cs.msk[rl];
        const unsigned long long w1 = cs.msk[rl + 8];
        const int shn = (lane & 3) * 2;
        const uint32_t a0  = (uint32_t)(w0 >> shn);
        const uint32_t a0h = (uint32_t)(w0 >> (shn + 32));
        const uint32_t a1  = (uint32_t)(w1 >> shn);
        const uint32_t a1h = (uint32_t)(w1 >> (shn + 32));

        // ---- P = exp2(S) fixed-max: select -> cvt -> ex2.f16x2 ----
        uint32_t pf[4][4];
        __half2 s0 = __floats2half2_rn(0.f, 0.f);
        __half2 s1 = s0;
#pragma unroll
        for (int kc2 = 0; kc2 < 4; kc2++) {
            const uint32_t ma = (kc2 < 2) ? a0 : a0h;   // row rl
            const uint32_t mb = (kc2 < 2) ? a1 : a1h;   // row rl+8
            const int s = (kc2 & 1) * 16;
            float t00 = (ma & (1u << (s + 0))) ? sv[kc2 * 2][0]     : NEG_INF;
            float t01 = (ma & (1u << (s + 1))) ? sv[kc2 * 2][1]     : NEG_INF;
            float t02 = (mb & (1u << (s + 0))) ? sv[kc2 * 2][2]     : NEG_INF;
            float t03 = (mb & (1u << (s + 1))) ? sv[kc2 * 2][3]     : NEG_INF;
            float t10 = (ma & (1u << (s + 8))) ? sv[kc2 * 2 + 1][0] : NEG_INF;
            float t11 = (ma & (1u << (s + 9))) ? sv[kc2 * 2 + 1][1] : NEG_INF;
            float t12 = (mb & (1u << (s + 8))) ? sv[kc2 * 2 + 1][2] : NEG_INF;
            float t13 = (mb & (1u << (s + 9))) ? sv[kc2 * 2 + 1][3] : NEG_INF;
            __half2 h00 = __floats2half2_rn(t00, t01);
            __half2 h01 = __floats2half2_rn(t02, t03);
            __half2 h10 = __floats2half2_rn(t10, t11);
            __half2 h11 = __floats2half2_rn(t12, t13);
            pf[kc2][0] = h2ex2(*(uint32_t*)&h00);
            pf[kc2][1] = h2ex2(*(uint32_t*)&h01);
            pf[kc2][2] = h2ex2(*(uint32_t*)&h10);
            pf[kc2][3] = h2ex2(*(uint32_t*)&h11);
            s0 = __hadd2(s0, __hadd2(*(__half2*)&pf[kc2][0], *(__half2*)&pf[kc2][2]));
            s1 = __hadd2(s1, __hadd2(*(__half2*)&pf[kc2][1], *(__half2*)&pf[kc2][3]));
        }
        lrow[0] += __low2float(s0) + __high2float(s0);
        lrow[1] += __low2float(s1) + __high2float(s1);

        // ---- O += P V (no rescale: fixed max) ----
#pragma unroll
        for (int dn2 = 0; dn2 < 4; dn2++) {
#pragma unroll
            for (int kc2 = 0; kc2 < 4; kc2++) {
                uint32_t vf[4];
                ldsm_x4_t(vf, smem_u32(
                    &cs.v[kc2 * 16 + (lane & 15)][dn2 * 16 + (lane >> 4) * 8]));
                mma16816(oacc[dn2 * 2],     pf[kc2], vf[0], vf[1]);
                mma16816(oacc[dn2 * 2 + 1], pf[kc2], vf[2], vf[3]);
            }
        }
    }

    // ---- l reduction (once) + finalize + store fp16 [B,T,H,d] ----
    lrow[0] += __shfl_xor_sync(0xffffffffu, lrow[0], 1);
    lrow[0] += __shfl_xor_sync(0xffffffffu, lrow[0], 2);
    lrow[1] += __shfl_xor_sync(0xffffffffu, lrow[1], 1);
    lrow[1] += __shfl_xor_sync(0xffffffffu, lrow[1], 2);
    const float inv0 = 1.f / lrow[0];
    const float inv1 = 1.f / lrow[1];
    const int qr = q0 + wid * 16 + (lane >> 2);
#pragma unroll
    for (int dn = 0; dn < 8; dn++) {
        const int d = dn * 8 + (lane & 3) * 2;
        __half2* o = (__half2*)out;
        const size_t e0 = ((size_t)b * T_ + qr) * (H_ * D_) + h * D_ + d;
        o[e0 >> 1] = __floats2half2_rn(oacc[dn][0] * inv0, oacc[dn][1] * inv0);
        const size_t e1 = e0 + (size_t)8 * H_ * D_;
        o[e1 >> 1] = __floats2half2_rn(oacc[dn][2] * inv1, oacc[dn][3] * inv1);
    }
}

// ---------------------------------------------------------------------------
extern "C" void kernel_launch(void* const* d_in, const int* in_sizes, int n_in,
                              void* d_out, int out_size)
{
    const float* query = (const float*)d_in[0];
    const float* key   = (const float*)d_in[1];
    const float* value = (const float*)d_in[2];
    const void*  mask  = d_in[3];
    const float* Wq = (const float*)d_in[4];
    const float* bq = (const float*)d_in[5];
    const float* Wk = (const float*)d_in[6];
    const float* bk = (const float*)d_in[7];
    const float* Wv = (const float*)d_in[8];
    const float* bv = (const float*)d_in[9];
    const float* Wo = (const float*)d_in[10];
    const float* bo = (const float*)d_in[11];
    float* out = (float*)d_out;

    __half *xq, *xk, *xv, *wq, *wk, *wv, *wo, *qh, *kh, *vh, *ah;
    unsigned long long* mb;
    cudaGetSymbolAddress((void**)&xq, g_xq);
    cudaGetSymbolAddress((void**)&xk, g_xk);
    cudaGetSymbolAddress((void**)&xv, g_xv);
    cudaGetSymbolAddress((void**)&wq, g_wq);
    cudaGetSymbolAddress((void**)&wk, g_wk);
    cudaGetSymbolAddress((void**)&wv, g_wv);
    cudaGetSymbolAddress((void**)&wo, g_wo);
    cudaGetSymbolAddress((void**)&qh, g_qh);
    cudaGetSymbolAddress((void**)&kh, g_kh);
    cudaGetSymbolAddress((void**)&vh, g_vh);
    cudaGetSymbolAddress((void**)&ah, g_ah);
    cudaGetSymbolAddress((void**)&mb, g_mb);

    cudaFuncSetAttribute(gemm_qkv,
        cudaFuncAttributeMaxDynamicSharedMemorySize, GEMM_SMEM);
    cudaFuncSetAttribute(gemm_out,
        cudaFuncAttributeMaxDynamicSharedMemorySize, GEMM_SMEM);
    cudaFuncSetAttribute(mha_attn,
        cudaFuncAttributeMaxDynamicSharedMemorySize, ATTN_SMEM);

    // launch 0: fused f32->f16 conversion + mask sniff/bitpack
    CvtArgs ca;
    ca.in[0] = query; ca.in[1] = key; ca.in[2] = value;
    ca.in[3] = Wq; ca.in[4] = Wk; ca.in[5] = Wv; ca.in[6] = Wo;
    ca.out[0] = xq; ca.out[1] = xk; ca.out[2] = xv;
    ca.out[3] = wq; ca.out[4] = wk; ca.out[5] = wv; ca.out[6] = wo;
    ca.mask_in = mask; ca.mask_out = mb;
    cvt_all<<<CVT_BLOCKS + MASK_BLOCKS, 256>>>(ca);

    // launch 1: QKV projections (Q scale folds softmax denom AND log2e)
    QKVArgs qa;
    qa.x[0] = xq; qa.x[1] = xk; qa.x[2] = xv;
    qa.w[0] = wq; qa.w[1] = wk; qa.w[2] = wv;
    qa.b[0] = bq; qa.b[1] = bk; qa.b[2] = bv;
    qa.o[0] = qh; qa.o[1] = kh; qa.o[2] = vh;
    qa.s[0] = DENOM * L2E; qa.s[1] = 1.0f; qa.s[2] = 1.0f;
    const dim3 pg(MODEL / 128, (B_ * T_) / 128, 3);   // (8, 64, 3)
    gemm_qkv<<<pg, 256, GEMM_SMEM>>>(qa);

    // launch 2: attention
    const dim3 ag(T_ / 128, H_, B_);                  // (16, 16, 4)
    mha_attn<<<ag, 256, ATTN_SMEM>>>(qh, kh, vh, mb, ah);

    // launch 3: output projection
    const dim3 og(MODEL / 128, (B_ * T_) / 128);      // (8, 64)
    gemm_out<<<og, 256, GEMM_SMEM>>>(ah, wo, bo, out);
}

// round 17
// speedup vs baseline: 1.0495x; 1.0495x over previous
#include <cuda_runtime.h>
#include <cuda_fp16.h>
#include <cstdint>

#define B_    4
#define T_    2048
#define H_    16
#define D_    64
#define MODEL 1024
#define DENOM 0.125f
#define NEG_INF (-1e30f)
#define L2E   1.4426950408889634f

// ---------------- scratch (allocation-free: device globals) ----------------
__device__ __half g_xq[(size_t)B_ * T_ * MODEL];
__device__ __half g_xk[(size_t)B_ * T_ * MODEL];
__device__ __half g_xv[(size_t)B_ * T_ * MODEL];
__device__ __half g_wq[(size_t)MODEL * MODEL];
__device__ __half g_wk[(size_t)MODEL * MODEL];
__device__ __half g_wv[(size_t)MODEL * MODEL];
__device__ __half g_wo[(size_t)MODEL * MODEL];
__device__ __half g_qh[(size_t)B_ * H_ * T_ * D_]; // Q, pre-scaled 0.125*log2e
__device__ __half g_kh[(size_t)B_ * H_ * T_ * D_]; // K [B,H,T,d]
__device__ __half g_vh[(size_t)B_ * H_ * T_ * D_]; // V [B,H,T,d]
__device__ __half g_ah[(size_t)B_ * T_ * H_ * D_]; // attn out [B,T,H,d]
// bitmask: word [b][kt][q] (kt = 64-key tile index), bit j = key kt*64+j
__device__ unsigned long long g_mb[(size_t)B_ * 32 * T_];

// ---------------------------------------------------------------------------
// Mask pack (separate launch, R15-proven): sniff dtype per block (first 4 KB),
// then pack 64 mask elements into one 64-bit word, layout [b][kt][q].
// ---------------------------------------------------------------------------
__global__ void mask_pack_kernel(const void* __restrict__ in,
                                 unsigned long long* __restrict__ out)
{
    __shared__ int red[8];
    __shared__ int s_flag;
    const int tid = threadIdx.x;

    uint4 v = ((const uint4*)in)[tid];          // first 4096 bytes
    const unsigned char* pb = (const unsigned char*)&v;
    int cnt = 0;
#pragma unroll
    for (int j = 0; j < 16; j++) cnt += (pb[j] != 0);
#pragma unroll
    for (int off = 16; off >= 1; off >>= 1)
        cnt += __shfl_xor_sync(0xffffffffu, cnt, off);
    if ((tid & 31) == 0) red[tid >> 5] = cnt;
    __syncthreads();
    if (tid == 0) {
        int total = 0;
#pragma unroll
        for (int w = 0; w < 8; w++) total += red[w];
        s_flag = (total > 1024) ? 1 : 0;        // 1 = byte mask
    }
    __syncthreads();

    const int w  = blockIdx.x * 256 + tid;      // word index, 262144 total
    const int b  = w >> 16;
    const int kt = (w >> 11) & 31;
    const int q  = w & (T_ - 1);
    const size_t ebase = ((size_t)b * T_ + q) * T_ + kt * 64;

    unsigned long long bits = 0;
    if (s_flag) {
        const uint32_t* s32 = (const uint32_t*)((const unsigned char*)in + ebase);
#pragma unroll
        for (int g = 0; g < 16; g++) {
            const uint32_t x = s32[g];
            if (x & 0x000000FFu) bits |= 1ull << (g * 4 + 0);
            if (x & 0x0000FF00u) bits |= 1ull << (g * 4 + 1);
            if (x & 0x00FF0000u) bits |= 1ull << (g * 4 + 2);
            if (x & 0xFF000000u) bits |= 1ull << (g * 4 + 3);
        }
    } else {
        const int* s32 = (const int*)in + ebase;
#pragma unroll
        for (int g = 0; g < 64; g++)
            if (s32[g]) bits |= 1ull << g;
    }
    out[w] = bits;
}

// fused f32->f16 conversion over 7 tensors (3 inputs + 4 weights)
#define NX4 (B_ * T_ * MODEL / 4)
#define NW4 (MODEL * MODEL / 4)
#define XBLK (NX4 / 256)
#define WBLK (NW4 / 256)
#define CVT_BLOCKS (3 * XBLK + 4 * WBLK)

struct CvtArgs { const float* in[7]; __half* out[7]; };

__global__ void cvt_all(CvtArgs a)
{
    int blk = blockIdx.x;
    int seg, base;
    if (blk < 3 * XBLK) { seg = blk / XBLK; base = (blk % XBLK); }
    else { blk -= 3 * XBLK; seg = 3 + blk / WBLK; base = (blk % WBLK); }
    const int i = base * 256 + threadIdx.x;
    float4 f = ((const float4*)a.in[seg])[i];
    __half2* o = (__half2*)a.out[seg];
    o[2 * i]     = __floats2half2_rn(f.x, f.y);
    o[2 * i + 1] = __floats2half2_rn(f.z, f.w);
}

// ------------------------- ptx wrappers -------------------------
__device__ __forceinline__ uint32_t smem_u32(const void* p)
{ return (uint32_t)__cvta_generic_to_shared(p); }

__device__ __forceinline__ void cp16(void* s, const void* g)
{
    asm volatile("cp.async.cg.shared.global [%0], [%1], 16;\n"
                 :: "r"(smem_u32(s)), "l"(g));
}
__device__ __forceinline__ void cp_commit()
{ asm volatile("cp.async.commit_group;\n"); }
template<int N> __device__ __forceinline__ void cp_wait()
{ asm volatile("cp.async.wait_group %0;\n" :: "n"(N)); }

__device__ __forceinline__ void ldsm_x4(uint32_t* r, uint32_t addr)
{
    asm volatile("ldmatrix.sync.aligned.m8n8.x4.shared.b16 {%0,%1,%2,%3}, [%4];\n"
                 : "=r"(r[0]), "=r"(r[1]), "=r"(r[2]), "=r"(r[3]) : "r"(addr));
}
__device__ __forceinline__ void ldsm_x4_t(uint32_t* r, uint32_t addr)
{
    asm volatile("ldmatrix.sync.aligned.m8n8.x4.trans.shared.b16 {%0,%1,%2,%3}, [%4];\n"
                 : "=r"(r[0]), "=r"(r[1]), "=r"(r[2]), "=r"(r[3]) : "r"(addr));
}
__device__ __forceinline__ void mma16816(float* d, const uint32_t* a,
                                         uint32_t b0, uint32_t b1)
{
    asm volatile(
        "mma.sync.aligned.m16n8k16.row.col.f32.f16.f16.f32 "
        "{%0,%1,%2,%3}, {%4,%5,%6,%7}, {%8,%9}, {%0,%1,%2,%3};\n"
        : "+f"(d[0]), "+f"(d[1]), "+f"(d[2]), "+f"(d[3])
        : "r"(a[0]), "r"(a[1]), "r"(a[2]), "r"(a[3]), "r"(b0), "r"(b1));
}

__device__ __forceinline__ uint32_t h2ex2(uint32_t x)
{
    uint32_t r;
    asm volatile("ex2.approx.f16x2 %0, %1;" : "=r"(r) : "r"(x));
    return r;
}

// ---------------------------------------------------------------------------
// fp16 tensor-core GEMM, cp.async 2-stage pipeline (R4-proven, unchanged).
// ---------------------------------------------------------------------------
#define GEMM_SMEM ((2 * 128 * 72 + 2 * 64 * 136) * 2)   // 71680 B

template<int MODE>
__device__ __forceinline__ void gemm_body(
    const __half* __restrict__ X, const __half* __restrict__ W,
    const float* __restrict__ bias, void* __restrict__ out, float oscale,
    char* dynsm)
{
    typedef __half ARow[72];
    typedef __half BRow[136];
    ARow* As0 = (ARow*)dynsm;
    ARow* As1 = (ARow*)(dynsm + 128 * 72 * 2);
    BRow* Bs0 = (BRow*)(dynsm + 2 * 128 * 72 * 2);
    BRow* Bs1 = (BRow*)(dynsm + 2 * 128 * 72 * 2 + 64 * 136 * 2);

    const int tid  = threadIdx.x;
    const int lane = tid & 31;
    const int wid  = tid >> 5;
    const int warp_m = wid >> 2;
    const int warp_n = wid & 3;
    const int m0 = blockIdx.y * 128;
    const int n0 = blockIdx.x * 128;

    const int ar = tid >> 3, ac = (tid & 7) * 8;
    const int br = tid >> 4, bc = (tid & 15) * 8;

    float acc[4][4][4];
#pragma unroll
    for (int i = 0; i < 4; i++)
#pragma unroll
        for (int j = 0; j < 4; j++)
#pragma unroll
            for (int r = 0; r < 4; r++) acc[i][j][r] = 0.f;

    {
#pragma unroll
        for (int p = 0; p < 4; p++)
            cp16(&As0[p * 32 + ar][ac], &X[(size_t)(m0 + p * 32 + ar) * MODEL + ac]);
#pragma unroll
        for (int p = 0; p < 4; p++)
            cp16(&Bs0[p * 16 + br][bc], &W[(size_t)(p * 16 + br) * MODEL + n0 + bc]);
        cp_commit();
    }

    const int NI = MODEL / 64;
    for (int i = 0; i < NI; i++) {
        cp_wait<0>();
        __syncthreads();
        if (i + 1 < NI) {
            const int k0 = (i + 1) * 64;
            ARow* An = (i & 1) ? As0 : As1;
            BRow* Bn = (i & 1) ? Bs0 : Bs1;
#pragma unroll
            for (int p = 0; p < 4; p++)
                cp16(&An[p * 32 + ar][ac], &X[(size_t)(m0 + p * 32 + ar) * MODEL + k0 + ac]);
#pragma unroll
            for (int p = 0; p < 4; p++)
                cp16(&Bn[p * 16 + br][bc], &W[(size_t)(k0 + p * 16 + br) * MODEL + n0 + bc]);
            cp_commit();
        }
        ARow* Ac = (i & 1) ? As1 : As0;
        BRow* Bc = (i & 1) ? Bs1 : Bs0;
#pragma unroll
        for (int ks = 0; ks < 4; ks++) {
            uint32_t af[4][4];
#pragma unroll
            for (int mi = 0; mi < 4; mi++)
                ldsm_x4(af[mi], smem_u32(
                    &Ac[warp_m * 64 + mi * 16 + (lane & 15)][ks * 16 + (lane >> 4) * 8]));
#pragma unroll
            for (int nj = 0; nj < 2; nj++) {
                uint32_t bf[4];
                ldsm_x4_t(bf, smem_u32(
                    &Bc[ks * 16 + (lane & 15)][warp_n * 32 + nj * 16 + (lane >> 4) * 8]));
#pragma unroll
                for (int mi = 0; mi < 4; mi++) {
                    mma16816(acc[mi][nj * 2],     af[mi], bf[0], bf[1]);
                    mma16816(acc[mi][nj * 2 + 1], af[mi], bf[2], bf[3]);
                }
            }
        }
    }

#pragma unroll
    for (int mi = 0; mi < 4; mi++) {
#pragma unroll
        for (int ni = 0; ni < 4; ni++) {
            const int row = m0 + warp_m * 64 + mi * 16 + (lane >> 2);
            const int col = n0 + warp_n * 32 + ni * 8 + (lane & 3) * 2;
            const float b0 = bias[col], b1 = bias[col + 1];
            float c0 = acc[mi][ni][0] + b0, c1 = acc[mi][ni][1] + b1;
            float c2 = acc[mi][ni][2] + b0, c3 = acc[mi][ni][3] + b1;
            if (MODE) {
                c0 *= oscale; c1 *= oscale; c2 *= oscale; c3 *= oscale;
                const int bb = row >> 11, t = row & (T_ - 1);
                const int hh = col >> 6,  d = col & 63;
                __half2* o = (__half2*)out;
                const size_t base = ((((size_t)bb * H_ + hh) * T_) + t) * D_ + d;
                o[base >> 1] = __floats2half2_rn(c0, c1);
                const size_t base2 = base + (size_t)8 * D_;
                o[base2 >> 1] = __floats2half2_rn(c2, c3);
            } else {
                float* o = (float*)out;
                *(float2*)&o[(size_t)row * MODEL + col] = make_float2(c0, c1);
                *(float2*)&o[(size_t)(row + 8) * MODEL + col] = make_float2(c2, c3);
            }
        }
    }
}

struct QKVArgs {
    const __half* x[3];
    const __half* w[3];
    const float*  b[3];
    __half*       o[3];
    float         s[3];
};

__global__ __launch_bounds__(256, 2) void gemm_qkv(QKVArgs a)
{
    extern __shared__ char dynsm[];
    const int z = blockIdx.z;
    gemm_body<1>(a.x[z], a.w[z], a.b[z], a.o[z], a.s[z], dynsm);
}

__global__ __launch_bounds__(256, 2) void gemm_out(
    const __half* __restrict__ X, const __half* __restrict__ W,
    const float* __restrict__ bias, float* __restrict__ out)
{
    extern __shared__ char dynsm[];
    gemm_body<0>(X, W, bias, out, 1.0f, dynsm);
}

// ---------------------------------------------------------------------------
// Flash attention (R15 base: fixed-max softmax, bitmask, 2 CTAs/SM) with:
//  - log2e folded into Q projection (S arrives in log2 domain: no FMULs)
//  - l reduction deferred out of the loop (no per-iter shuffles)
// ---------------------------------------------------------------------------
struct AStage {
    __half k[64][72];
    __half v[64][72];
    unsigned long long msk[128];   // 1 KB bitmask
};  // 19456 B
#define ATTN_SMEM (128 * 72 * 2 + 2 * (int)sizeof(AStage))   // 57344 B

__global__ __launch_bounds__(256, 2) void mha_attn(
    const __half* __restrict__ qg, const __half* __restrict__ kg,
    const __half* __restrict__ vg, const unsigned long long* __restrict__ mbit,
    __half* __restrict__ out)
{
    extern __shared__ char dynsm[];
    typedef __half QRow[72];
    QRow* Qs = (QRow*)dynsm;                          // [128][72]
    AStage* st = (AStage*)(dynsm + 128 * 72 * 2);     // [2]

    const int tid  = threadIdx.x;
    const int lane = tid & 31;
    const int wid  = tid >> 5;
    const int q0 = blockIdx.x * 128;
    const int h  = blockIdx.y;
    const int b  = blockIdx.z;

    const __half* gq = qg + (((size_t)b * H_ + h) * T_ + q0) * D_;
    const __half* gk = kg + (((size_t)b * H_ + h) * T_) * D_;
    const __half* gv = vg + (((size_t)b * H_ + h) * T_) * D_;
    const unsigned long long* gmb = mbit + (size_t)b * 32 * T_ + q0;

    const int kvr = tid >> 3, kvc = (tid & 7) * 8;

    auto load_stage = [&](int kt, int stage) {
        AStage& ns = st[stage];
        const __half* gkt = gk + (size_t)kt * 64 * D_;
        const __half* gvt = gv + (size_t)kt * 64 * D_;
#pragma unroll
        for (int p = 0; p < 2; p++) {
            cp16(&ns.k[p * 32 + kvr][kvc], &gkt[(size_t)(p * 32 + kvr) * D_ + kvc]);
            cp16(&ns.v[p * 32 + kvr][kvc], &gvt[(size_t)(p * 32 + kvr) * D_ + kvc]);
        }
        if (tid < 64)
            cp16(&ns.msk[tid * 2], &gmb[(size_t)kt * T_ + tid * 2]);
    };

    // ---- prologue: Q tile, then stage 0 ----
#pragma unroll
    for (int p = 0; p < 4; p++)
        cp16(&Qs[p * 32 + kvr][kvc], &gq[(size_t)(p * 32 + kvr) * D_ + kvc]);
    cp_commit();
    load_stage(0, 0);
    cp_commit();

    cp_wait<1>();
    __syncthreads();
    uint32_t qf[4][4];
#pragma unroll
    for (int kc = 0; kc < 4; kc++)
        ldsm_x4(qf[kc], smem_u32(
            &Qs[wid * 16 + (lane & 15)][kc * 16 + (lane >> 4) * 8]));

    float oacc[8][4];
#pragma unroll
    for (int i = 0; i < 8; i++)
#pragma unroll
        for (int r = 0; r < 4; r++) oacc[i][r] = 0.f;
    float lrow[2] = {0.f, 0.f};    // per-thread partials; reduced after loop

    const int NT = T_ / 64;   // 32
    for (int kt = 0; kt < NT; kt++) {
        cp_wait<0>();
        __syncthreads();
        if (kt + 1 < NT) {
            load_stage(kt + 1, (kt + 1) & 1);
            cp_commit();
        }
        AStage& cs = st[kt & 1];

        // ---- S = Q K^T (Q pre-scaled by 0.125*log2e: S is log2-domain) ----
        float sv[8][4];
#pragma unroll
        for (int i = 0; i < 8; i++)
#pragma unroll
            for (int r = 0; r < 4; r++) sv[i][r] = 0.f;
#pragma unroll
        for (int nt2 = 0; nt2 < 4; nt2++) {
#pragma unroll
            for (int kc = 0; kc < 4; kc++) {
                uint32_t kf[4];
                ldsm_x4(kf, smem_u32(
                    &cs.k[nt2 * 16 + (lane & 15)][kc * 16 + (lane >> 4) * 8]));
                mma16816(sv[nt2 * 2],     qf[kc], kf[0], kf[2]);
                mma16816(sv[nt2 * 2 + 1], qf[kc], kf[1], kf[3]);
            }
        }

        // ---- bitmask fetch: 2 x LDS.64, pre-shift by this thread's column ----
        const int rl = wid * 16 + (lane >> 2);
        const unsigned long long w0 = cs.msk[rl];
        const unsigned long long w1 = cs.msk[rl + 8];
        const int shn = (lane & 3) * 2;
        const uint32_t a0  = (uint32_t)(w0 >> shn);
        const uint32_t a0h = (uint32_t)(w0 >> (shn + 32));
        const uint32_t a1  = (uint32_t)(w1 >> shn);
        const uint32_t a1h = (uint32_t)(w1 >> (shn + 32));

        // ---- P = exp2(S) fixed-max: select -> cvt -> ex2.f16x2 ----
        uint32_t pf[4][4];
        __half2 s0 = __floats2half2_rn(0.f, 0.f);
        __half2 s1 = s0;
#pragma unroll
        for (int kc2 = 0; kc2 < 4; kc2++) {
            const uint32_t ma = (kc2 < 2) ? a0 : a0h;   // row rl
            const uint32_t mb = (kc2 < 2) ? a1 : a1h;   // row rl+8
            const int s = (kc2 & 1) * 16;
            float t00 = (ma & (1u << (s + 0))) ? sv[kc2 * 2][0]     : NEG_INF;
            float t01 = (ma & (1u << (s + 1))) ? sv[kc2 * 2][1]     : NEG_INF;
            float t02 = (mb & (1u << (s + 0))) ? sv[kc2 * 2][2]     : NEG_INF;
            float t03 = (mb & (1u << (s + 1))) ? sv[kc2 * 2][3]     : NEG_INF;
            float t10 = (ma & (1u << (s + 8))) ? sv[kc2 * 2 + 1][0] : NEG_INF;
            float t11 = (ma & (1u << (s + 9))) ? sv[kc2 * 2 + 1][1] : NEG_INF;
            float t12 = (mb & (1u << (s + 8))) ? sv[kc2 * 2 + 1][2] : NEG_INF;
            float t13 = (mb & (1u << (s + 9))) ? sv[kc2 * 2 + 1][3] : NEG_INF;
            __half2 h00 = __floats2half2_rn(t00, t01);
            __half2 h01 = __floats2half2_rn(t02, t03);
            __half2 h10 = __floats2half2_rn(t10, t11);
            __half2 h11 = __floats2half2_rn(t12, t13);
            pf[kc2][0] = h2ex2(*(uint32_t*)&h00);
            pf[kc2][1] = h2ex2(*(uint32_t*)&h01);
            pf[kc2][2] = h2ex2(*(uint32_t*)&h10);
            pf[kc2][3] = h2ex2(*(uint32_t*)&h11);
            s0 = __hadd2(s0, __hadd2(*(__half2*)&pf[kc2][0], *(__half2*)&pf[kc2][2]));
            s1 = __hadd2(s1, __hadd2(*(__half2*)&pf[kc2][1], *(__half2*)&pf[kc2][3]));
        }
        lrow[0] += __low2float(s0) + __high2float(s0);
        lrow[1] += __low2float(s1) + __high2float(s1);

        // ---- O += P V (no rescale: fixed max) ----
#pragma unroll
        for (int dn2 = 0; dn2 < 4; dn2++) {
#pragma unroll
            for (int kc2 = 0; kc2 < 4; kc2++) {
                uint32_t vf[4];
                ldsm_x4_t(vf, smem_u32(
                    &cs.v[kc2 * 16 + (lane & 15)][dn2 * 16 + (lane >> 4) * 8]));
                mma16816(oacc[dn2 * 2],     pf[kc2], vf[0], vf[1]);
                mma16816(oacc[dn2 * 2 + 1], pf[kc2], vf[2], vf[3]);
            }
        }
    }

    // ---- l reduction (once) + finalize + store fp16 [B,T,H,d] ----
    lrow[0] += __shfl_xor_sync(0xffffffffu, lrow[0], 1);
    lrow[0] += __shfl_xor_sync(0xffffffffu, lrow[0], 2);
    lrow[1] += __shfl_xor_sync(0xffffffffu, lrow[1], 1);
    lrow[1] += __shfl_xor_sync(0xffffffffu, lrow[1], 2);
    const float inv0 = 1.f / lrow[0];
    const float inv1 = 1.f / lrow[1];
    const int qr = q0 + wid * 16 + (lane >> 2);
#pragma unroll
    for (int dn = 0; dn < 8; dn++) {
        const int d = dn * 8 + (lane & 3) * 2;
        __half2* o = (__half2*)out;
        const size_t e0 = ((size_t)b * T_ + qr) * (H_ * D_) + h * D_ + d;
        o[e0 >> 1] = __floats2half2_rn(oacc[dn][0] * inv0, oacc[dn][1] * inv0);
        const size_t e1 = e0 + (size_t)8 * H_ * D_;
        o[e1 >> 1] = __floats2half2_rn(oacc[dn][2] * inv1, oacc[dn][3] * inv1);
    }
}

// ---------------------------------------------------------------------------
extern "C" void kernel_launch(void* const* d_in, const int* in_sizes, int n_in,
                              void* d_out, int out_size)
{
    const float* query = (const float*)d_in[0];
    const float* key   = (const float*)d_in[1];
    const float* value = (const float*)d_in[2];
    const void*  mask  = d_in[3];
    const float* Wq = (const float*)d_in[4];
    const float* bq = (const float*)d_in[5];
    const float* Wk = (const float*)d_in[6];
    const float* bk = (const float*)d_in[7];
    const float* Wv = (const float*)d_in[8];
    const float* bv = (const float*)d_in[9];
    const float* Wo = (const float*)d_in[10];
    const float* bo = (const float*)d_in[11];
    float* out = (float*)d_out;

    __half *xq, *xk, *xv, *wq, *wk, *wv, *wo, *qh, *kh, *vh, *ah;
    unsigned long long* mb;
    cudaGetSymbolAddress((void**)&xq, g_xq);
    cudaGetSymbolAddress((void**)&xk, g_xk);
    cudaGetSymbolAddress((void**)&xv, g_xv);
    cudaGetSymbolAddress((void**)&wq, g_wq);
    cudaGetSymbolAddress((void**)&wk, g_wk);
    cudaGetSymbolAddress((void**)&wv, g_wv);
    cudaGetSymbolAddress((void**)&wo, g_wo);
    cudaGetSymbolAddress((void**)&qh, g_qh);
    cudaGetSymbolAddress((void**)&kh, g_kh);
    cudaGetSymbolAddress((void**)&vh, g_vh);
    cudaGetSymbolAddress((void**)&ah, g_ah);
    cudaGetSymbolAddress((void**)&mb, g_mb);

    cudaFuncSetAttribute(gemm_qkv,
        cudaFuncAttributeMaxDynamicSharedMemorySize, GEMM_SMEM);
    cudaFuncSetAttribute(gemm_out,
        cudaFuncAttributeMaxDynamicSharedMemorySize, GEMM_SMEM);
    cudaFuncSetAttribute(mha_attn,
        cudaFuncAttributeMaxDynamicSharedMemorySize, ATTN_SMEM);

    // launch 0: mask sniff + bitpack
    mask_pack_kernel<<<(B_ * 32 * T_) / 256, 256>>>(mask, mb);

    // launch 1: input/weight conversion
    CvtArgs ca;
    ca.in[0] = query; ca.in[1] = key; ca.in[2] = value;
    ca.in[3] = Wq; ca.in[4] = Wk; ca.in[5] = Wv; ca.in[6] = Wo;
    ca.out[0] = xq; ca.out[1] = xk; ca.out[2] = xv;
    ca.out[3] = wq; ca.out[4] = wk; ca.out[5] = wv; ca.out[6] = wo;
    cvt_all<<<CVT_BLOCKS, 256>>>(ca);

    // launch 2: QKV projections (Q scale folds softmax denom AND log2e)
    QKVArgs qa;
    qa.x[0] = xq; qa.x[1] = xk; qa.x[2] = xv;
    qa.w[0] = wq; qa.w[1] = wk; qa.w[2] = wv;
    qa.b[0] = bq; qa.b[1] = bk; qa.b[2] = bv;
    qa.o[0] = qh; qa.o[1] = kh; qa.o[2] = vh;
    qa.s[0] = DENOM * L2E; qa.s[1] = 1.0f; qa.s[2] = 1.0f;
    const dim3 pg(MODEL / 128, (B_ * T_) / 128, 3);   // (8, 64, 3)
    gemm_qkv<<<pg, 256, GEMM_SMEM>>>(qa);

    // launch 3: attention (ncu captures this one)
    const dim3 ag(T_ / 128, H_, B_);                  // (16, 16, 4)
    mha_attn<<<ag, 256, ATTN_SMEM>>>(qh, kh, vh, mb, ah);

    // launch 4: output projection
    const dim3 og(MODEL / 128, (B_ * T_) / 128);      // (8, 64)
    gemm_out<<<og, 256, GEMM_SMEM>>>(ah, wo, bo, out);
}